// round 12
// baseline (speedup 1.0000x reference)
#include <cuda_runtime.h>

#define H 8192
#define T 64
#define PINROWS 4096   // hi-bytes of rows < PINROWS pinned in L2 (32 MB) + all lo (32 MB)

// ---- __device__ scratch (no allocations allowed) ----
__device__ float g_pre[T * H];                              // 2 MB
__device__ signed char g_Whi[(size_t)H * H];                // 64 MB hi bytes (q>>4)
__device__ unsigned char g_Wlo[(size_t)H * H / 2];          // 32 MB lo nibbles
__device__ float g_scale[H];                                // rowmax/(2047*32767)
__device__ __align__(16) short g_hq[2][H];                  // int16 h double buffer

// ---------------------------------------------------------------------------
// f32x2 helpers
// ---------------------------------------------------------------------------
__device__ __forceinline__ void ffma2(unsigned long long& d,
                                      unsigned long long a,
                                      unsigned long long b)
{
    asm("fma.rn.f32x2 %0, %1, %2, %3;" : "=l"(d) : "l"(a), "l"(b), "l"(d));
}
__device__ __forceinline__ unsigned long long dup2(float a)
{
    unsigned long long r;
    asm("mov.b64 %0, {%1, %1};" : "=l"(r) : "r"(__float_as_int(a)));
    return r;
}
__device__ __forceinline__ float2 unpack2(unsigned long long v)
{
    float2 f;
    f.x = __int_as_float((int)(v & 0xffffffffu));
    f.y = __int_as_float((int)(v >> 32));
    return f;
}

// ---------------------------------------------------------------------------
// GEMM: pre = x @ W_ih^T + b.  (unchanged, near f32x2 floor)
// ---------------------------------------------------------------------------
__global__ __launch_bounds__(256) void gemm_pre_kernel(
    const float* __restrict__ x,
    const float* __restrict__ W,
    const float* __restrict__ b)
{
    const int BN = 64, BK = 16;
    __shared__ float As[BK][64];
    __shared__ float Bs[BK][BN];

    int tid = threadIdx.x;
    int n0  = blockIdx.x * BN;
    int tx  = tid & 15;
    int ty  = tid >> 4;
    int lr  = tid >> 2;
    int lk  = (tid & 3) * 4;

    unsigned long long acc[4][2];
    #pragma unroll
    for (int i = 0; i < 4; i++) { acc[i][0] = 0ull; acc[i][1] = 0ull; }

    for (int k0 = 0; k0 < H; k0 += BK) {
        float4 av = *(const float4*)(x + (size_t)lr * H + k0 + lk);
        float4 bv = *(const float4*)(W + (size_t)(n0 + lr) * H + k0 + lk);
        __syncthreads();
        As[lk + 0][lr] = av.x; As[lk + 1][lr] = av.y;
        As[lk + 2][lr] = av.z; As[lk + 3][lr] = av.w;
        Bs[lk + 0][lr] = bv.x; Bs[lk + 1][lr] = bv.y;
        Bs[lk + 2][lr] = bv.z; Bs[lk + 3][lr] = bv.w;
        __syncthreads();

        #pragma unroll
        for (int kk = 0; kk < BK; kk++) {
            float4 af = *(const float4*)&As[kk][ty * 4];
            ulonglong2 bb = *(const ulonglong2*)&Bs[kk][tx * 4];
            unsigned long long am[4] = { dup2(af.x), dup2(af.y),
                                         dup2(af.z), dup2(af.w) };
            #pragma unroll
            for (int i = 0; i < 4; i++) {
                ffma2(acc[i][0], am[i], bb.x);
                ffma2(acc[i][1], am[i], bb.y);
            }
        }
    }

    #pragma unroll
    for (int i = 0; i < 4; i++) {
        int m = ty * 4 + i;
        #pragma unroll
        for (int j = 0; j < 2; j++) {
            int n = n0 + tx * 4 + 2 * j;
            float2 p = unpack2(acc[i][j]);
            p.x += b[n];
            p.y += b[n + 1];
            *(float2*)&g_pre[(size_t)m * H + n] = p;
        }
    }
}

// ---------------------------------------------------------------------------
// Quantize W_hh -> 12-bit packed for dp2a. hi of rows >= PINROWS stored with
// .cs (streaming) so the pinned-intended lines survive in L2 until the loop.
// ---------------------------------------------------------------------------
__global__ __launch_bounds__(256) void quant_kernel(const float* __restrict__ W)
{
    __shared__ float red[8];
    int row = blockIdx.x;
    int tid = threadIdx.x;
    const float4* w4 = (const float4*)(W + (size_t)row * H);

    float4 va[4], vb[4];
    float m = 0.f;
    #pragma unroll
    for (int k = 0; k < 4; k++) {
        int g = tid + k * 256;          // 8-weight group index 0..1023
        va[k] = w4[2 * g];
        vb[k] = w4[2 * g + 1];
        m = fmaxf(m, fmaxf(fmaxf(fabsf(va[k].x), fabsf(va[k].y)),
                           fmaxf(fabsf(va[k].z), fabsf(va[k].w))));
        m = fmaxf(m, fmaxf(fmaxf(fabsf(vb[k].x), fabsf(vb[k].y)),
                           fmaxf(fabsf(vb[k].z), fabsf(vb[k].w))));
    }
    #pragma unroll
    for (int o = 16; o; o >>= 1)
        m = fmaxf(m, __shfl_xor_sync(0xffffffffu, m, o));
    if ((tid & 31) == 0) red[tid >> 5] = m;
    __syncthreads();
    float rowmax = fmaxf(fmaxf(fmaxf(red[0], red[1]), fmaxf(red[2], red[3])),
                         fmaxf(fmaxf(red[4], red[5]), fmaxf(red[6], red[7])));
    rowmax = fmaxf(rowmax, 1e-30f);
    float inv = 2047.0f / rowmax;

    uint2*    hi2 = (uint2*)(g_Whi + (size_t)row * H);
    unsigned* lo4 = (unsigned*)(g_Wlo + (size_t)row * (H / 2));

    #pragma unroll
    for (int k = 0; k < 4; k++) {
        int g = tid + k * 256;
        int q[8];
        q[0] = max(-2047, min(2047, __float2int_rn(va[k].x * inv)));
        q[1] = max(-2047, min(2047, __float2int_rn(va[k].y * inv)));
        q[2] = max(-2047, min(2047, __float2int_rn(va[k].z * inv)));
        q[3] = max(-2047, min(2047, __float2int_rn(va[k].w * inv)));
        q[4] = max(-2047, min(2047, __float2int_rn(vb[k].x * inv)));
        q[5] = max(-2047, min(2047, __float2int_rn(vb[k].y * inv)));
        q[6] = max(-2047, min(2047, __float2int_rn(vb[k].z * inv)));
        q[7] = max(-2047, min(2047, __float2int_rn(vb[k].w * inv)));

        unsigned w0 = ((unsigned)((q[0] >> 4) & 0xFF))
                    | ((unsigned)((q[1] >> 4) & 0xFF) << 8)
                    | ((unsigned)((q[2] >> 4) & 0xFF) << 16)
                    | ((unsigned)((q[3] >> 4) & 0xFF) << 24);
        unsigned w1 = ((unsigned)((q[4] >> 4) & 0xFF))
                    | ((unsigned)((q[5] >> 4) & 0xFF) << 8)
                    | ((unsigned)((q[6] >> 4) & 0xFF) << 16)
                    | ((unsigned)((q[7] >> 4) & 0xFF) << 24);
        unsigned lw = (unsigned)(q[0] & 15)
                    | ((unsigned)(q[4] & 15) << 4)
                    | ((unsigned)(q[1] & 15) << 8)
                    | ((unsigned)(q[5] & 15) << 12)
                    | ((unsigned)(q[2] & 15) << 16)
                    | ((unsigned)(q[6] & 15) << 20)
                    | ((unsigned)(q[3] & 15) << 24)
                    | ((unsigned)(q[7] & 15) << 28);
        if (row < PINROWS) {
            hi2[g] = make_uint2(w0, w1);
        } else {
            asm volatile("st.global.cs.v2.u32 [%0], {%1,%2};"
                         :: "l"(hi2 + g), "r"(w0), "r"(w1) : "memory");
        }
        lo4[g] = lw;
    }
    if (tid == 0) g_scale[row] = rowmax / (2047.0f * 32767.0f);
}

// ---------------------------------------------------------------------------
// t = 0: h0 = 0 -> out[0][n] = tanh(pre[0][n]); also int16-quantize h.
// ---------------------------------------------------------------------------
__global__ void step0_kernel(float* __restrict__ out)
{
    int i = blockIdx.x * blockDim.x + threadIdx.x;
    float h = tanhf(g_pre[i]);
    out[i] = h;
    g_hq[0][i] = (short)__float2int_rn(h * 32767.0f);
}

// ---------------------------------------------------------------------------
// Recurrence step, dp2a, 16 weights/lane/iter (LDG.128 hi + LDG.64 lo).
// lo (32 MB) and hi rows < PINROWS (32 MB) loaded evict_last (pin in L2);
// remaining hi loaded evict_first (pure stream, no pollution).
// ---------------------------------------------------------------------------
__global__ __launch_bounds__(512) void gemv_q_kernel(
    float* __restrict__ h_out,   // = out + t*H
    int t)
{
    __shared__ uint4 shA[H / 16];   // h int16x2 words 8g..8g+3   (weights 16g..16g+7)
    __shared__ uint4 shB[H / 16];   // h int16x2 words 8g+4..8g+7 (weights 16g+8..16g+15)

    int tid = threadIdx.x;
    const uint4* hq4 = (const uint4*)g_hq[(t - 1) & 1];
    #pragma unroll
    for (int k = 0; k < 2; k++) {
        int j = tid + k * 512;              // half-group index 0..1023
        uint4 v = hq4[j];
        if (j & 1) shB[j >> 1] = v; else shA[j >> 1] = v;
    }
    __syncthreads();

    int warp = tid >> 5;
    int lane = tid & 31;
    int row  = blockIdx.x * 16 + warp;

    unsigned long long polL, polF;
    asm("createpolicy.fractional.L2::evict_last.b64 %0, 1.0;"  : "=l"(polL));
    asm("createpolicy.fractional.L2::evict_first.b64 %0, 1.0;" : "=l"(polF));
    unsigned long long polHi = (row < PINROWS) ? polL : polF;

    const uint4* hi4 = (const uint4*)(g_Whi + (size_t)row * H);
    const uint2* lo2 = (const uint2*)(g_Wlo + (size_t)row * (H / 2));

    int accH = 0, accL = 0;
    #pragma unroll 4
    for (int i = lane; i < H / 16; i += 32) {     // 16 iters, 16 weights each
        unsigned h0, h1, h2, h3, l0, l1;
        asm("ld.global.nc.L2::cache_hint.v4.u32 {%0,%1,%2,%3}, [%4], %5;"
            : "=r"(h0), "=r"(h1), "=r"(h2), "=r"(h3)
            : "l"(hi4 + i), "l"(polHi));
        asm("ld.global.nc.L2::cache_hint.v2.u32 {%0,%1}, [%2], %3;"
            : "=r"(l0), "=r"(l1) : "l"(lo2 + i), "l"(polL));
        uint4 ha = shA[i];
        uint4 hb = shB[i];

        unsigned a0 = l0 & 0x0F0F0F0Fu, a1 = (l0 >> 4) & 0x0F0F0F0Fu;
        unsigned c0 = l1 & 0x0F0F0F0Fu, c1 = (l1 >> 4) & 0x0F0F0F0Fu;

        asm("dp2a.lo.s32.s32 %0, %1, %2, %0;" : "+r"(accH) : "r"(ha.x), "r"(h0));
        asm("dp2a.hi.s32.s32 %0, %1, %2, %0;" : "+r"(accH) : "r"(ha.y), "r"(h0));
        asm("dp2a.lo.s32.s32 %0, %1, %2, %0;" : "+r"(accH) : "r"(ha.z), "r"(h1));
        asm("dp2a.hi.s32.s32 %0, %1, %2, %0;" : "+r"(accH) : "r"(ha.w), "r"(h1));
        asm("dp2a.lo.s32.s32 %0, %1, %2, %0;" : "+r"(accH) : "r"(hb.x), "r"(h2));
        asm("dp2a.hi.s32.s32 %0, %1, %2, %0;" : "+r"(accH) : "r"(hb.y), "r"(h2));
        asm("dp2a.lo.s32.s32 %0, %1, %2, %0;" : "+r"(accH) : "r"(hb.z), "r"(h3));
        asm("dp2a.hi.s32.s32 %0, %1, %2, %0;" : "+r"(accH) : "r"(hb.w), "r"(h3));

        asm("dp2a.lo.s32.u32 %0, %1, %2, %0;" : "+r"(accL) : "r"(ha.x), "r"(a0));
        asm("dp2a.hi.s32.u32 %0, %1, %2, %0;" : "+r"(accL) : "r"(ha.y), "r"(a0));
        asm("dp2a.lo.s32.u32 %0, %1, %2, %0;" : "+r"(accL) : "r"(ha.z), "r"(a1));
        asm("dp2a.hi.s32.u32 %0, %1, %2, %0;" : "+r"(accL) : "r"(ha.w), "r"(a1));
        asm("dp2a.lo.s32.u32 %0, %1, %2, %0;" : "+r"(accL) : "r"(hb.x), "r"(c0));
        asm("dp2a.hi.s32.u32 %0, %1, %2, %0;" : "+r"(accL) : "r"(hb.y), "r"(c0));
        asm("dp2a.lo.s32.u32 %0, %1, %2, %0;" : "+r"(accL) : "r"(hb.z), "r"(c1));
        asm("dp2a.hi.s32.u32 %0, %1, %2, %0;" : "+r"(accL) : "r"(hb.w), "r"(c1));
    }

    float acc = fmaf(16.0f, (float)accH, (float)accL);
    #pragma unroll
    for (int o = 16; o; o >>= 1)
        acc += __shfl_xor_sync(0xffffffffu, acc, o);

    if (lane == 0) {
        float h = tanhf(acc * g_scale[row] + g_pre[t * H + row]);
        h_out[row] = h;
        g_hq[t & 1][row] = (short)__float2int_rn(h * 32767.0f);
    }
}

// ---------------------------------------------------------------------------
extern "C" void kernel_launch(void* const* d_in, const int* in_sizes, int n_in,
                              void* d_out, int out_size)
{
    const float* x    = (const float*)d_in[0];   // (64, 8192)
    const float* W_ih = (const float*)d_in[1];   // (8192, 8192)
    const float* W_hh = (const float*)d_in[2];   // (8192, 8192)
    const float* b    = (const float*)d_in[3];   // (8192,)
    float* out = (float*)d_out;                  // (64*8192,) fp32

    (void)in_sizes; (void)n_in; (void)out_size;

    gemm_pre_kernel<<<H / 64, 256>>>(x, W_ih, b);
    quant_kernel<<<H, 256>>>(W_hh);              // last before steps: L2-warm
    step0_kernel<<<H / 256, 256>>>(out);
    for (int t = 1; t < T; t++) {
        gemv_q_kernel<<<H / 16, 512>>>(out + (size_t)t * H, t);
    }
}